// round 14
// baseline (speedup 1.0000x reference)
#include <cuda_runtime.h>
#include <cuda_bf16.h>

#define NN   4096
#define FIN  256
#define C1   512     // H1 * HID
#define H1   8
#define HID  64
#define OUT2 128
#define MAXN 512
#define NT1  33      // tile-boundary offsets per row

// ---------------- scratch (no allocations allowed) ----------------
__device__ float g_h1[NN * C1];
__device__ uint4 g_h1b[NN * C1 / 8];
__device__ float g_hmid[NN * C1];
__device__ float g_h2[NN * OUT2];
__device__ uint4 g_h2b[NN * OUT2 / 8];
__device__ float g_asrc1[NN * H1];
__device__ float g_adst1[NN * H1];
__device__ float g_p2s[2 * NN];
__device__ float g_p2d[2 * NN];
__device__ unsigned short g_nbr[NN * MAXN];
__device__ unsigned short g_toff[NN * NT1];
__device__ int g_cnt[NN];

__device__ __forceinline__ float bflo(unsigned u) { return __uint_as_float(u << 16); }
__device__ __forceinline__ float bfhi(unsigned u) { return __uint_as_float(u & 0xffff0000u); }

__device__ __forceinline__ unsigned f2tf(float f) {
    unsigned u; asm("cvt.rna.tf32.f32 %0, %1;" : "=r"(u) : "f"(f)); return u;
}

#define MMA_TF32(d, a, b)                                                  \
    asm volatile(                                                          \
        "mma.sync.aligned.m16n8k8.row.col.f32.tf32.tf32.f32 "              \
        "{%0,%1,%2,%3}, {%4,%5,%6,%7}, {%8,%9}, {%0,%1,%2,%3};"            \
        : "+f"(d[0]), "+f"(d[1]), "+f"(d[2]), "+f"(d[3])                   \
        : "r"(a[0]), "r"(a[1]), "r"(a[2]), "r"(a[3]), "r"(b[0]), "r"(b[1]))

#define MMA_BF16(d, a, b)                                                  \
    asm volatile(                                                          \
        "mma.sync.aligned.m16n8k16.row.col.f32.bf16.bf16.f32 "             \
        "{%0,%1,%2,%3}, {%4,%5,%6,%7}, {%8,%9}, {%0,%1,%2,%3};"            \
        : "+f"(d[0]), "+f"(d[1]), "+f"(d[2]), "+f"(d[3])                   \
        : "r"(a[0]), "r"(a[1]), "r"(a[2]), "r"(a[3]), "r"(b[0]), "r"(b[1]))

__device__ __forceinline__ void ldmx4(unsigned* r, unsigned a) {
    asm volatile("ldmatrix.sync.aligned.m8n8.x4.shared.b16 {%0,%1,%2,%3}, [%4];"
                 : "=r"(r[0]), "=r"(r[1]), "=r"(r[2]), "=r"(r[3]) : "r"(a));
}
__device__ __forceinline__ void ldmx2t(unsigned* r, unsigned a) {
    asm volatile("ldmatrix.sync.aligned.m8n8.x2.trans.shared.b16 {%0,%1}, [%2];"
                 : "=r"(r[0]), "=r"(r[1]) : "r"(a));
}

// ---------------- CSR build (deterministic, ordered) + tile offsets ----------------
__global__ void build_csr(const float* __restrict__ adj) {
    int row = blockIdx.x;
    int t   = threadIdx.x;                 // 256
    const float* arow = adj + (size_t)row * NN;
    int base = t * 16;

    float av[16];
    #pragma unroll
    for (int q = 0; q < 4; q++) {
        float4 v = *(const float4*)(arow + base + q * 4);
        av[q * 4 + 0] = v.x; av[q * 4 + 1] = v.y;
        av[q * 4 + 2] = v.z; av[q * 4 + 3] = v.w;
    }
    int cnt = 0;
    #pragma unroll
    for (int k = 0; k < 16; k++) cnt += (av[k] != 0.0f);

    __shared__ int s[256];
    s[t] = cnt;
    __syncthreads();
    for (int off = 1; off < 256; off <<= 1) {
        int v = (t >= off) ? s[t - off] : 0;
        __syncthreads();
        s[t] += v;
        __syncthreads();
    }
    int pos = s[t] - cnt;
    unsigned short* out = g_nbr + (size_t)row * MAXN;
    #pragma unroll
    for (int k = 0; k < 16; k++) {
        if (av[k] != 0.0f) {
            if (pos < MAXN) out[pos] = (unsigned short)(base + k);
            pos++;
        }
    }
    int total = (s[255] < MAXN) ? s[255] : MAXN;
    if (t == 255) g_cnt[row] = total;
    __syncthreads();
    // per-row tile boundaries: first index with nbr >= b*128 (list is sorted)
    if (t <= 32) {
        int target = t * 128;
        int lo = 0, hi = total;
        while (lo < hi) {
            int mid = (lo + hi) >> 1;
            if (out[mid] < target) lo = mid + 1; else hi = mid;
        }
        g_toff[row * NT1 + t] = (unsigned short)lo;
    }
}

// ---------- tf32 tensor-core GEMM + fused attention-score epilogue ----------
template <int BM, int BN, int WM, int WN, int MT, int NT, int NSEG, bool DIRECT>
__global__ __launch_bounds__(256) void gemm_tf32(
    const float* __restrict__ A, const float* __restrict__ B,
    float* __restrict__ C, __nv_bfloat162* __restrict__ Cb,
    const float* __restrict__ att_s, const float* __restrict__ att_d,
    float* __restrict__ sA, float* __restrict__ sD,
    int M, int N, int K)
{
    const int BK = 32;
    const int WCOLS = BN / WN;
    const int WPS = WCOLS / NSEG;
    __shared__ unsigned As[BM][36];
    __shared__ unsigned Bs[BK][BN + 8];
    __shared__ float s_ss[BM][WCOLS];
    __shared__ float s_dd[BM][WCOLS];
    int tid  = threadIdx.x;
    int lane = tid & 31;
    int warp = tid >> 5;
    int wx = warp % WCOLS, wy = warp / WCOLS;
    int wm = wy * WM;
    int wn = wx * WN;
    int m0 = blockIdx.y * BM, n0 = blockIdx.x * BN;
    int g = lane >> 2, t4 = lane & 3;

    float acc[MT][NT][4];
    #pragma unroll
    for (int mt = 0; mt < MT; mt++)
        #pragma unroll
        for (int nt = 0; nt < NT; nt++)
            #pragma unroll
            for (int q = 0; q < 4; q++) acc[mt][nt][q] = 0.0f;

    const int A4T = BM / 32;
    const int B4T = BN / 32;
    float4 pa[A4T], pb[B4T];

    #pragma unroll
    for (int i = 0; i < A4T; i++) {
        int idx = tid + i * 256;
        pa[i] = *(const float4*)&A[(size_t)(m0 + (idx >> 3)) * K + (idx & 7) * 4];
    }
    #pragma unroll
    for (int i = 0; i < B4T; i++) {
        int idx = tid + i * 256;
        pb[i] = *(const float4*)&B[(size_t)(idx / (BN / 4)) * N + n0 + (idx % (BN / 4)) * 4];
    }

    for (int kt = 0; kt < K; kt += BK) {
        #pragma unroll
        for (int i = 0; i < A4T; i++) {
            int idx = tid + i * 256;
            uint4 u = make_uint4(f2tf(pa[i].x), f2tf(pa[i].y), f2tf(pa[i].z), f2tf(pa[i].w));
            *(uint4*)&As[idx >> 3][(idx & 7) * 4] = u;
        }
        #pragma unroll
        for (int i = 0; i < B4T; i++) {
            int idx = tid + i * 256;
            uint4 u = make_uint4(f2tf(pb[i].x), f2tf(pb[i].y), f2tf(pb[i].z), f2tf(pb[i].w));
            *(uint4*)&Bs[idx / (BN / 4)][(idx % (BN / 4)) * 4] = u;
        }
        __syncthreads();

        if (kt + BK < K) {
            #pragma unroll
            for (int i = 0; i < A4T; i++) {
                int idx = tid + i * 256;
                pa[i] = *(const float4*)&A[(size_t)(m0 + (idx >> 3)) * K + kt + BK + (idx & 7) * 4];
            }
            #pragma unroll
            for (int i = 0; i < B4T; i++) {
                int idx = tid + i * 256;
                pb[i] = *(const float4*)&B[(size_t)(kt + BK + idx / (BN / 4)) * N + n0 + (idx % (BN / 4)) * 4];
            }
        }

        #pragma unroll
        for (int ks = 0; ks < 4; ks++) {
            int ko = ks * 8;
            unsigned af[MT][4], bf[NT][2];
            #pragma unroll
            for (int mt = 0; mt < MT; mt++) {
                int r = wm + mt * 16 + g;
                af[mt][0] = As[r][ko + t4];
                af[mt][1] = As[r + 8][ko + t4];
                af[mt][2] = As[r][ko + t4 + 4];
                af[mt][3] = As[r + 8][ko + t4 + 4];
            }
            #pragma unroll
            for (int nt = 0; nt < NT; nt++) {
                int c = wn + nt * 8 + g;
                bf[nt][0] = Bs[ko + t4][c];
                bf[nt][1] = Bs[ko + t4 + 4][c];
            }
            #pragma unroll
            for (int mt = 0; mt < MT; mt++)
                #pragma unroll
                for (int nt = 0; nt < NT; nt++)
                    MMA_TF32(acc[mt][nt], af[mt], bf[nt]);
        }
        __syncthreads();
    }

    #pragma unroll
    for (int mt = 0; mt < MT; mt++) {
        #pragma unroll
        for (int nt = 0; nt < NT; nt++) {
            int r = m0 + wm + mt * 16 + g;
            int c = n0 + wn + nt * 8 + t4 * 2;
            size_t o0 = (size_t)r * N + c;
            size_t o1 = (size_t)(r + 8) * N + c;
            *(float2*)&C[o0] = make_float2(acc[mt][nt][0], acc[mt][nt][1]);
            *(float2*)&C[o1] = make_float2(acc[mt][nt][2], acc[mt][nt][3]);
            Cb[o0 >> 1] = __floats2bfloat162_rn(acc[mt][nt][0], acc[mt][nt][1]);
            Cb[o1 >> 1] = __floats2bfloat162_rn(acc[mt][nt][2], acc[mt][nt][3]);
        }
    }

    float asv[NT][2], adv[NT][2];
    #pragma unroll
    for (int nt = 0; nt < NT; nt++) {
        int c = n0 + wn + nt * 8 + t4 * 2;
        asv[nt][0] = att_s[c]; asv[nt][1] = att_s[c + 1];
        adv[nt][0] = att_d[c]; adv[nt][1] = att_d[c + 1];
    }
    #pragma unroll
    for (int mt = 0; mt < MT; mt++) {
        #pragma unroll
        for (int half = 0; half < 2; half++) {
            float ss = 0.0f, dd = 0.0f;
            #pragma unroll
            for (int nt = 0; nt < NT; nt++) {
                ss += acc[mt][nt][2 * half] * asv[nt][0] + acc[mt][nt][2 * half + 1] * asv[nt][1];
                dd += acc[mt][nt][2 * half] * adv[nt][0] + acc[mt][nt][2 * half + 1] * adv[nt][1];
            }
            #pragma unroll
            for (int off = 1; off < 4; off <<= 1) {
                ss += __shfl_xor_sync(0xffffffffu, ss, off);
                dd += __shfl_xor_sync(0xffffffffu, dd, off);
            }
            if (t4 == 0) {
                int rl = wm + mt * 16 + g + half * 8;
                s_ss[rl][wx] = ss;
                s_dd[rl][wx] = dd;
            }
        }
    }
    __syncthreads();
    for (int idx = tid; idx < BM * NSEG; idx += 256) {
        int rl = idx % BM, seg = idx / BM;
        float ss = 0.0f, dd = 0.0f;
        #pragma unroll
        for (int w = 0; w < WPS; w++) {
            ss += s_ss[rl][seg * WPS + w];
            dd += s_dd[rl][seg * WPS + w];
        }
        if (DIRECT) {
            int h = blockIdx.x * NSEG + seg;
            sA[(size_t)(m0 + rl) * H1 + h] = ss;
            sD[(size_t)(m0 + rl) * H1 + h] = dd;
        } else {
            size_t o = (size_t)(blockIdx.x * NSEG + seg) * NN + m0 + rl;
            sA[o] = ss;
            sD[o] = dd;
        }
    }
}

// ---------------- layer-1 aggregation: tiled bf16 tensor-core SpMM ----------------
// CTA = (row-block ib of 128, head h). alpha tile [128i][128j] built sparsely,
// out[128, 64] += alpha @ H_h-tile. H traffic: 256*32*16KB = 128MB (was 840MB).
#define ASTR 136
#define HSTR 72
#define SM_ALPHA 0
#define SM_HS    (128 * ASTR * 2)                    // 34816
#define SM_ADST  (SM_HS + 128 * HSTR * 2)            // +18432 = 53248
#define SM_DEN   (SM_ADST + 128 * 4)                 // +512   = 53760
#define SM_TOT   (SM_DEN + 256 * 4)                  // +1024  = 54784

__global__ __launch_bounds__(256) void agg1_mma(const float* __restrict__ b1) {
    extern __shared__ char smem[];
    __nv_bfloat16* alpha = (__nv_bfloat16*)(smem + SM_ALPHA);   // [128][ASTR]
    __nv_bfloat16* Hs    = (__nv_bfloat16*)(smem + SM_HS);      // [128][HSTR]
    float* adst_s        = (float*)(smem + SM_ADST);            // [128]
    float* den_s         = (float*)(smem + SM_DEN);             // [2][128]

    int ib = blockIdx.x, h = blockIdx.y;
    int tid = threadIdx.x, lane = tid & 31, warp = tid >> 5;
    int wm = (warp >> 1) * 32, wn = (warp & 1) * 32;
    int g = lane >> 2, t4 = lane & 3;

    if (tid < 128) adst_s[tid] = g_adst1[(ib * 128 + tid) * H1 + h];

    int il = tid >> 1, half = tid & 1;
    int row = ib * 128 + il;
    float denp = 0.0f;

    float acc[2][4][4];
    #pragma unroll
    for (int mt = 0; mt < 2; mt++)
        #pragma unroll
        for (int nt = 0; nt < 4; nt++)
            #pragma unroll
            for (int q = 0; q < 4; q++) acc[mt][nt][q] = 0.0f;

    unsigned alpha_u = (unsigned)__cvta_generic_to_shared(alpha);
    unsigned hs_u    = (unsigned)__cvta_generic_to_shared(Hs);
    __syncthreads();   // adst_s visible

    for (int jb = 0; jb < 32; jb++) {
        // zero alpha tile + stage H tile (raw [j][c] layout; ldmatrix.trans does the transpose)
        uint4 z = make_uint4(0, 0, 0, 0);
        for (int k = tid; k < 128 * ASTR / 8; k += 256) ((uint4*)alpha)[k] = z;
        for (int k = tid; k < 1024; k += 256) {
            int jl = k >> 3, q = k & 7;
            uint4 v = g_h1b[(size_t)(jb * 128 + jl) * 64 + h * 8 + q];
            *(uint4*)&Hs[jl * HSTR + q * 8] = v;
        }
        __syncthreads();

        // scatter edge weights into alpha tile (2 threads per row, fixed partition)
        {
            int off0 = g_toff[row * NT1 + jb];
            int off1 = g_toff[row * NT1 + jb + 1];
            float ad = adst_s[il];
            for (int e = off0 + half; e < off1; e += 2) {
                int j = g_nbr[row * MAXN + e];
                float v = g_asrc1[j * H1 + h] + ad;
                v = v > 0.0f ? v : 0.2f * v;
                float w = __expf(v);
                denp += w;
                alpha[il * ASTR + (j - jb * 128)] = __float2bfloat16(w);
            }
        }
        __syncthreads();

        // dense MMA over the tile: out[128,64] += alpha[128,128] @ Hs[128,64]
        #pragma unroll
        for (int ks = 0; ks < 8; ks++) {
            int k0 = ks * 16;
            unsigned af[2][4], bf[4][2];
            #pragma unroll
            for (int mt = 0; mt < 2; mt++) {
                int r = wm + mt * 16 + (lane & 15);
                ldmx4(af[mt], alpha_u + (r * ASTR + k0 + ((lane >> 4) << 3)) * 2);
            }
            #pragma unroll
            for (int nt = 0; nt < 4; nt++) {
                int kk = k0 + (lane & 15);
                ldmx2t(bf[nt], hs_u + (kk * HSTR + wn + nt * 8) * 2);
            }
            #pragma unroll
            for (int mt = 0; mt < 2; mt++)
                #pragma unroll
                for (int nt = 0; nt < 4; nt++)
                    MMA_BF16(acc[mt][nt], af[mt], bf[nt]);
        }
        __syncthreads();
    }

    den_s[half * 128 + il] = denp;
    __syncthreads();

    // epilogue: divide by softmax denom, bias, leaky, write hmid fp32
    #pragma unroll
    for (int mt = 0; mt < 2; mt++) {
        #pragma unroll
        for (int nt = 0; nt < 4; nt++) {
            int r0 = wm + mt * 16 + g;
            int c  = wn + nt * 8 + t4 * 2;
            int ch = h * HID + c;
            float bb0 = b1[ch], bb1 = b1[ch + 1];
            float dn0 = den_s[r0] + den_s[128 + r0];
            float dn1 = den_s[r0 + 8] + den_s[128 + r0 + 8];
            float o0 = acc[mt][nt][0] / dn0 + bb0;
            float o1 = acc[mt][nt][1] / dn0 + bb1;
            float o2 = acc[mt][nt][2] / dn1 + bb0;
            float o3 = acc[mt][nt][3] / dn1 + bb1;
            o0 = o0 > 0.0f ? o0 : 0.01f * o0;
            o1 = o1 > 0.0f ? o1 : 0.01f * o1;
            o2 = o2 > 0.0f ? o2 : 0.01f * o2;
            o3 = o3 > 0.0f ? o3 : 0.01f * o3;
            *(float2*)&g_hmid[(size_t)(ib * 128 + r0) * C1 + ch]     = make_float2(o0, o1);
            *(float2*)&g_hmid[(size_t)(ib * 128 + r0 + 8) * C1 + ch] = make_float2(o2, o3);
        }
    }
}

// ---------------- layer-2 sparse aggregation (reduce2 folded in) ----------------
__global__ void __launch_bounds__(256) agg2(const float* __restrict__ b2,
                                            float* __restrict__ out) {
    int i = blockIdx.x;
    int t = threadIdx.x;                  // 256
    __shared__ unsigned short s_nbr[MAXN];
    __shared__ float s_w[MAXN];
    __shared__ float s_part[256];
    __shared__ float s_den;
    __shared__ float s_red[16][8][16];    // 8KB

    int cnt = g_cnt[i];
    for (int jj = t; jj < cnt; jj += 256) s_nbr[jj] = g_nbr[(size_t)i * MAXN + jj];
    __syncthreads();

    float adst = g_p2d[i] + g_p2d[NN + i];
    for (int jj = t; jj < cnt; jj += 256) {
        int j = s_nbr[jj];
        float v = (g_p2s[j] + g_p2s[NN + j]) + adst;
        v = v > 0.0f ? v : 0.2f * v;
        s_w[jj] = __expf(v);
    }
    __syncthreads();

    float s = 0.0f;
    for (int jj = t; jj < cnt; jj += 256) s += s_w[jj];
    s_part[t] = s;
    __syncthreads();
    for (int off = 128; off >= 1; off >>= 1) {
        if (t < off) s_part[t] += s_part[t + off];
        __syncthreads();
    }
    if (t == 0) s_den = s_part[0];
    __syncthreads();

    {
        int c8 = t & 15;
        int g  = t >> 4;                  // 0..15
        float acc[8] = {0, 0, 0, 0, 0, 0, 0, 0};
        for (int jj = g; jj < cnt; jj += 16) {
            int j = s_nbr[jj];
            uint4 v = g_h2b[(size_t)j * (OUT2 / 8) + c8];
            float w = s_w[jj];
            acc[0] += w * bflo(v.x); acc[1] += w * bfhi(v.x);
            acc[2] += w * bflo(v.y); acc[3] += w * bfhi(v.y);
            acc[4] += w * bflo(v.z); acc[5] += w * bfhi(v.z);
            acc[6] += w * bflo(v.w); acc[7] += w * bfhi(v.w);
        }
        #pragma unroll
        for (int k = 0; k < 8; k++) s_red[g][k][c8] = acc[k];
        __syncthreads();

        if (t < 16) {
            float inv = 1.0f / s_den;
            float o[8];
            #pragma unroll
            for (int k = 0; k < 8; k++) {
                float ss = 0.0f;
                #pragma unroll
                for (int gg = 0; gg < 16; gg++) ss += s_red[gg][k][t];
                float v = ss * inv + b2[t * 8 + k];
                o[k] = v > 0.0f ? v : 0.01f * v;
            }
            float4* dst = (float4*)&out[(size_t)i * OUT2 + t * 8];
            dst[0] = make_float4(o[0], o[1], o[2], o[3]);
            dst[1] = make_float4(o[4], o[5], o[6], o[7]);
        }
    }
}

// ---------------- launch ----------------
extern "C" void kernel_launch(void* const* d_in, const int* in_sizes, int n_in,
                              void* d_out, int out_size) {
    const float* x   = (const float*)d_in[0];
    const float* adj = (const float*)d_in[1];
    const float* w1  = (const float*)d_in[2];
    const float* as1 = (const float*)d_in[3];
    const float* ad1 = (const float*)d_in[4];
    const float* b1  = (const float*)d_in[5];
    const float* w2  = (const float*)d_in[6];
    const float* as2 = (const float*)d_in[7];
    const float* ad2 = (const float*)d_in[8];
    const float* b2  = (const float*)d_in[9];
    float* out = (float*)d_out;

    float *h1p, *hmidp, *h2p, *asrc1p, *adst1p, *p2sp, *p2dp;
    __nv_bfloat162 *h1bp, *h2bp;
    cudaGetSymbolAddress((void**)&h1p,    g_h1);
    cudaGetSymbolAddress((void**)&hmidp,  g_hmid);
    cudaGetSymbolAddress((void**)&h2p,    g_h2);
    cudaGetSymbolAddress((void**)&h1bp,   g_h1b);
    cudaGetSymbolAddress((void**)&h2bp,   g_h2b);
    cudaGetSymbolAddress((void**)&asrc1p, g_asrc1);
    cudaGetSymbolAddress((void**)&adst1p, g_adst1);
    cudaGetSymbolAddress((void**)&p2sp,   g_p2s);
    cudaGetSymbolAddress((void**)&p2dp,   g_p2d);

    cudaFuncSetAttribute(agg1_mma, cudaFuncAttributeMaxDynamicSharedMemorySize, SM_TOT);

    build_csr<<<NN, 256>>>(adj);

    // h1 = x @ w1 (tf32 MMA + bf16 copy + fused scores1)
    gemm_tf32<64, 128, 32, 32, 2, 4, 2, true><<<dim3(C1 / 128, NN / 64), 256>>>(
        x, w1, h1p, h1bp, as1, ad1, asrc1p, adst1p, NN, C1, FIN);

    // layer-1 aggregation via tiled bf16 tensor-core SpMM
    agg1_mma<<<dim3(32, H1), 256, SM_TOT>>>(b1);

    // h2 = hmid @ w2 (tf32 MMA + bf16 copy + fused score partials)
    gemm_tf32<32, 64, 16, 16, 1, 2, 1, false><<<dim3(OUT2 / 64, NN / 32), 256>>>(
        hmidp, w2, h2p, h2bp, as2, ad2, p2sp, p2dp, NN, OUT2, C1);

    agg2<<<NN, 256>>>(b2, out);
}

// round 17
// speedup vs baseline: 1.4511x; 1.4511x over previous
#include <cuda_runtime.h>
#include <cuda_bf16.h>

#define NN   4096
#define FIN  256
#define C1   512     // H1 * HID
#define H1   8
#define HID  64
#define OUT2 128
#define MAXN 512
#define WPAD (MAXN + 4)

// ---------------- scratch (no allocations allowed) ----------------
__device__ float g_h1[NN * C1];          // layer-1 features fp32
__device__ uint4 g_h1b[NN * C1 / 8];     // layer-1 features bf16 (gather)
__device__ float g_hmid[NN * C1];        // layer-1 output fp32
__device__ float g_h2[NN * OUT2];        // layer-2 features fp32
__device__ uint4 g_h2b[NN * OUT2 / 8];   // layer-2 features bf16 (gather)
__device__ float g_asrc1[NN * H1];
__device__ float g_adst1[NN * H1];
__device__ float g_p2s[2 * NN];          // gemm2 score partials
__device__ float g_p2d[2 * NN];
__device__ unsigned short g_nbr[NN * MAXN];
__device__ int g_cnt[NN];

__device__ __forceinline__ float bflo(unsigned u) { return __uint_as_float(u << 16); }
__device__ __forceinline__ float bfhi(unsigned u) { return __uint_as_float(u & 0xffff0000u); }

__device__ __forceinline__ unsigned f2tf(float f) {
    unsigned u; asm("cvt.rna.tf32.f32 %0, %1;" : "=r"(u) : "f"(f)); return u;
}

#define MMA_TF32(d, a, b)                                                  \
    asm volatile(                                                          \
        "mma.sync.aligned.m16n8k8.row.col.f32.tf32.tf32.f32 "              \
        "{%0,%1,%2,%3}, {%4,%5,%6,%7}, {%8,%9}, {%0,%1,%2,%3};"            \
        : "+f"(d[0]), "+f"(d[1]), "+f"(d[2]), "+f"(d[3])                   \
        : "r"(a[0]), "r"(a[1]), "r"(a[2]), "r"(a[3]), "r"(b[0]), "r"(b[1]))

// ---------------- CSR build (deterministic, ordered) ----------------
__global__ void build_csr(const float* __restrict__ adj) {
    int row = blockIdx.x;
    int t   = threadIdx.x;                 // 256
    const float* arow = adj + (size_t)row * NN;
    int base = t * 16;

    float av[16];
    #pragma unroll
    for (int q = 0; q < 4; q++) {
        float4 v = *(const float4*)(arow + base + q * 4);
        av[q * 4 + 0] = v.x; av[q * 4 + 1] = v.y;
        av[q * 4 + 2] = v.z; av[q * 4 + 3] = v.w;
    }
    int cnt = 0;
    #pragma unroll
    for (int k = 0; k < 16; k++) cnt += (av[k] != 0.0f);

    __shared__ int s[256];
    s[t] = cnt;
    __syncthreads();
    for (int off = 1; off < 256; off <<= 1) {
        int v = (t >= off) ? s[t - off] : 0;
        __syncthreads();
        s[t] += v;
        __syncthreads();
    }
    int pos = s[t] - cnt;
    unsigned short* out = g_nbr + (size_t)row * MAXN;
    #pragma unroll
    for (int k = 0; k < 16; k++) {
        if (av[k] != 0.0f) {
            if (pos < MAXN) out[pos] = (unsigned short)(base + k);
            pos++;
        }
    }
    if (t == 255) g_cnt[row] = (s[255] < MAXN) ? s[255] : MAXN;
}

// ---------- tf32 tensor-core GEMM + fused attention-score epilogue ----------
// 256 threads = 8 warps (BM/WM rows x BN/WN cols). Templated BK.
// NSEG 64-col score segments per block; DIRECT: write g_asrc/adst [row*H1+head],
// else per-block partials sA[(bx*NSEG+seg)*NN + row].
template <int BM, int BN, int BK, int WM, int WN, int MT, int NT, int NSEG, bool DIRECT>
__global__ __launch_bounds__(256) void gemm_tf32(
    const float* __restrict__ A, const float* __restrict__ B,
    float* __restrict__ C, __nv_bfloat162* __restrict__ Cb,
    const float* __restrict__ att_s, const float* __restrict__ att_d,
    float* __restrict__ sA, float* __restrict__ sD,
    int M, int N, int K)
{
    const int WCOLS = BN / WN;
    const int WPS = WCOLS / NSEG;          // warps per score segment
    __shared__ unsigned As[BM][BK + 4];
    __shared__ unsigned Bs[BK][BN + 8];
    __shared__ float s_ss[BM][WCOLS];
    __shared__ float s_dd[BM][WCOLS];
    int tid  = threadIdx.x;
    int lane = tid & 31;
    int warp = tid >> 5;
    int wx = warp % WCOLS, wy = warp / WCOLS;
    int wm = wy * WM;
    int wn = wx * WN;
    int m0 = blockIdx.y * BM, n0 = blockIdx.x * BN;
    int g = lane >> 2, t4 = lane & 3;

    float acc[MT][NT][4];
    #pragma unroll
    for (int mt = 0; mt < MT; mt++)
        #pragma unroll
        for (int nt = 0; nt < NT; nt++)
            #pragma unroll
            for (int q = 0; q < 4; q++) acc[mt][nt][q] = 0.0f;

    const int A4T = BM * BK / (4 * 256);
    const int B4T = BK * BN / (4 * 256);
    const int KQ = BK / 4;
    float4 pa[A4T], pb[B4T];

    #pragma unroll
    for (int i = 0; i < A4T; i++) {
        int idx = tid + i * 256;
        pa[i] = *(const float4*)&A[(size_t)(m0 + idx / KQ) * K + (idx % KQ) * 4];
    }
    #pragma unroll
    for (int i = 0; i < B4T; i++) {
        int idx = tid + i * 256;
        pb[i] = *(const float4*)&B[(size_t)(idx / (BN / 4)) * N + n0 + (idx % (BN / 4)) * 4];
    }

    for (int kt = 0; kt < K; kt += BK) {
        #pragma unroll
        for (int i = 0; i < A4T; i++) {
            int idx = tid + i * 256;
            uint4 u = make_uint4(f2tf(pa[i].x), f2tf(pa[i].y), f2tf(pa[i].z), f2tf(pa[i].w));
            *(uint4*)&As[idx / KQ][(idx % KQ) * 4] = u;
        }
        #pragma unroll
        for (int i = 0; i < B4T; i++) {
            int idx = tid + i * 256;
            uint4 u = make_uint4(f2tf(pb[i].x), f2tf(pb[i].y), f2tf(pb[i].z), f2tf(pb[i].w));
            *(uint4*)&Bs[idx / (BN / 4)][(idx % (BN / 4)) * 4] = u;
        }
        __syncthreads();

        if (kt + BK < K) {
            #pragma unroll
            for (int i = 0; i < A4T; i++) {
                int idx = tid + i * 256;
                pa[i] = *(const float4*)&A[(size_t)(m0 + idx / KQ) * K + kt + BK + (idx % KQ) * 4];
            }
            #pragma unroll
            for (int i = 0; i < B4T; i++) {
                int idx = tid + i * 256;
                pb[i] = *(const float4*)&B[(size_t)(kt + BK + idx / (BN / 4)) * N + n0 + (idx % (BN / 4)) * 4];
            }
        }

        #pragma unroll
        for (int ks = 0; ks < BK / 8; ks++) {
            int ko = ks * 8;
            unsigned af[MT][4], bf[NT][2];
            #pragma unroll
            for (int mt = 0; mt < MT; mt++) {
                int r = wm + mt * 16 + g;
                af[mt][0] = As[r][ko + t4];
                af[mt][1] = As[r + 8][ko + t4];
                af[mt][2] = As[r][ko + t4 + 4];
                af[mt][3] = As[r + 8][ko + t4 + 4];
            }
            #pragma unroll
            for (int nt = 0; nt < NT; nt++) {
                int c = wn + nt * 8 + g;
                bf[nt][0] = Bs[ko + t4][c];
                bf[nt][1] = Bs[ko + t4 + 4][c];
            }
            #pragma unroll
            for (int mt = 0; mt < MT; mt++)
                #pragma unroll
                for (int nt = 0; nt < NT; nt++)
                    MMA_TF32(acc[mt][nt], af[mt], bf[nt]);
        }
        __syncthreads();
    }

    // ---- epilogue: fp32 + bf16 stores ----
    #pragma unroll
    for (int mt = 0; mt < MT; mt++) {
        #pragma unroll
        for (int nt = 0; nt < NT; nt++) {
            int r = m0 + wm + mt * 16 + g;
            int c = n0 + wn + nt * 8 + t4 * 2;
            size_t o0 = (size_t)r * N + c;
            size_t o1 = (size_t)(r + 8) * N + c;
            *(float2*)&C[o0] = make_float2(acc[mt][nt][0], acc[mt][nt][1]);
            *(float2*)&C[o1] = make_float2(acc[mt][nt][2], acc[mt][nt][3]);
            Cb[o0 >> 1] = __floats2bfloat162_rn(acc[mt][nt][0], acc[mt][nt][1]);
            Cb[o1 >> 1] = __floats2bfloat162_rn(acc[mt][nt][2], acc[mt][nt][3]);
        }
    }

    // ---- fused attention scores ----
    float asv[NT][2], adv[NT][2];
    #pragma unroll
    for (int nt = 0; nt < NT; nt++) {
        int c = n0 + wn + nt * 8 + t4 * 2;
        asv[nt][0] = att_s[c]; asv[nt][1] = att_s[c + 1];
        adv[nt][0] = att_d[c]; adv[nt][1] = att_d[c + 1];
    }
    #pragma unroll
    for (int mt = 0; mt < MT; mt++) {
        #pragma unroll
        for (int half = 0; half < 2; half++) {
            float ss = 0.0f, dd = 0.0f;
            #pragma unroll
            for (int nt = 0; nt < NT; nt++) {
                ss += acc[mt][nt][2 * half] * asv[nt][0] + acc[mt][nt][2 * half + 1] * asv[nt][1];
                dd += acc[mt][nt][2 * half] * adv[nt][0] + acc[mt][nt][2 * half + 1] * adv[nt][1];
            }
            #pragma unroll
            for (int off = 1; off < 4; off <<= 1) {
                ss += __shfl_xor_sync(0xffffffffu, ss, off);
                dd += __shfl_xor_sync(0xffffffffu, dd, off);
            }
            if (t4 == 0) {
                int rl = wm + mt * 16 + g + half * 8;
                s_ss[rl][wx] = ss;
                s_dd[rl][wx] = dd;
            }
        }
    }
    __syncthreads();
    for (int idx = tid; idx < BM * NSEG; idx += 256) {
        int rl = idx % BM, seg = idx / BM;
        float ss = 0.0f, dd = 0.0f;
        #pragma unroll
        for (int w = 0; w < WPS; w++) {
            ss += s_ss[rl][seg * WPS + w];
            dd += s_dd[rl][seg * WPS + w];
        }
        if (DIRECT) {
            int h = blockIdx.x * NSEG + seg;
            sA[(size_t)(m0 + rl) * H1 + h] = ss;
            sD[(size_t)(m0 + rl) * H1 + h] = dd;
        } else {
            size_t o = (size_t)(blockIdx.x * NSEG + seg) * NN + m0 + rl;
            sA[o] = ss;
            sD[o] = dd;
        }
    }
}

// ---------------- layer-1 sparse aggregation (bf16 uint4 gather) ----------------
__global__ void __launch_bounds__(512) agg1(const float* __restrict__ b1) {
    int i = blockIdx.x;
    int t = threadIdx.x;                  // 512
    __shared__ unsigned short s_nbr[MAXN];
    __shared__ float s_w[H1][WPAD];
    __shared__ float s_part[H1 * 64];
    __shared__ float s_den[H1];
    __shared__ float s_red[8][8][64];     // 16KB

    int cnt = g_cnt[i];
    for (int jj = t; jj < cnt; jj += 512) s_nbr[jj] = g_nbr[(size_t)i * MAXN + jj];
    __syncthreads();

    float adst[H1];
    {
        float4 d0 = *(const float4*)&g_adst1[i * H1];
        float4 d1 = *(const float4*)&g_adst1[i * H1 + 4];
        adst[0] = d0.x; adst[1] = d0.y; adst[2] = d0.z; adst[3] = d0.w;
        adst[4] = d1.x; adst[5] = d1.y; adst[6] = d1.z; adst[7] = d1.w;
    }
    for (int jj = t; jj < cnt; jj += 512) {
        int j = s_nbr[jj];
        float4 a0 = *(const float4*)&g_asrc1[j * H1];
        float4 a1 = *(const float4*)&g_asrc1[j * H1 + 4];
        float av[H1] = {a0.x, a0.y, a0.z, a0.w, a1.x, a1.y, a1.z, a1.w};
        #pragma unroll
        for (int h = 0; h < H1; h++) {
            float v = av[h] + adst[h];
            v = v > 0.0f ? v : 0.2f * v;
            s_w[h][jj] = __expf(v);
        }
    }
    __syncthreads();

    {
        int h = t >> 6, k = t & 63;
        float s = 0.0f;
        for (int jj = k; jj < cnt; jj += 64) s += s_w[h][jj];
        s_part[t] = s;
        __syncthreads();
        for (int off = 32; off >= 1; off >>= 1) {
            if (k < off) s_part[t] += s_part[t + off];
            __syncthreads();
        }
        if (k == 0) s_den[h] = s_part[t];
        __syncthreads();
    }

    {
        int c8 = t & 63;
        int g  = t >> 6;                  // 0..7
        int h  = c8 >> 3;
        const float* wrow = s_w[h];
        float acc[8] = {0, 0, 0, 0, 0, 0, 0, 0};
        for (int jj = g; jj < cnt; jj += 8) {
            int j = s_nbr[jj];
            uint4 v = g_h1b[(size_t)j * (C1 / 8) + c8];
            float w = wrow[jj];
            acc[0] += w * bflo(v.x); acc[1] += w * bfhi(v.x);
            acc[2] += w * bflo(v.y); acc[3] += w * bfhi(v.y);
            acc[4] += w * bflo(v.z); acc[5] += w * bfhi(v.z);
            acc[6] += w * bflo(v.w); acc[7] += w * bfhi(v.w);
        }
        #pragma unroll
        for (int k = 0; k < 8; k++) s_red[g][k][c8] = acc[k];
        __syncthreads();

        if (t < 64) {
            float inv = 1.0f / s_den[t >> 3];
            float o[8];
            #pragma unroll
            for (int k = 0; k < 8; k++) {
                float s = 0.0f;
                #pragma unroll
                for (int gg = 0; gg < 8; gg++) s += s_red[gg][k][t];
                float v = s * inv + b1[t * 8 + k];
                o[k] = v > 0.0f ? v : 0.01f * v;
            }
            float4* dst = (float4*)&g_hmid[(size_t)i * C1 + t * 8];
            dst[0] = make_float4(o[0], o[1], o[2], o[3]);
            dst[1] = make_float4(o[4], o[5], o[6], o[7]);
        }
    }
}

// ---------------- layer-2 sparse aggregation (reduce2 folded in) ----------------
__global__ void __launch_bounds__(256) agg2(const float* __restrict__ b2,
                                            float* __restrict__ out) {
    int i = blockIdx.x;
    int t = threadIdx.x;                  // 256
    __shared__ unsigned short s_nbr[MAXN];
    __shared__ float s_w[MAXN];
    __shared__ float s_part[256];
    __shared__ float s_den;
    __shared__ float s_red[16][8][16];    // 8KB

    int cnt = g_cnt[i];
    for (int jj = t; jj < cnt; jj += 256) s_nbr[jj] = g_nbr[(size_t)i * MAXN + jj];
    __syncthreads();

    float adst = g_p2d[i] + g_p2d[NN + i];
    for (int jj = t; jj < cnt; jj += 256) {
        int j = s_nbr[jj];
        float v = (g_p2s[j] + g_p2s[NN + j]) + adst;
        v = v > 0.0f ? v : 0.2f * v;
        s_w[jj] = __expf(v);
    }
    __syncthreads();

    float s = 0.0f;
    for (int jj = t; jj < cnt; jj += 256) s += s_w[jj];
    s_part[t] = s;
    __syncthreads();
    for (int off = 128; off >= 1; off >>= 1) {
        if (t < off) s_part[t] += s_part[t + off];
        __syncthreads();
    }
    if (t == 0) s_den = s_part[0];
    __syncthreads();

    {
        int c8 = t & 15;
        int g  = t >> 4;                  // 0..15
        float acc[8] = {0, 0, 0, 0, 0, 0, 0, 0};
        for (int jj = g; jj < cnt; jj += 16) {
            int j = s_nbr[jj];
            uint4 v = g_h2b[(size_t)j * (OUT2 / 8) + c8];
            float w = s_w[jj];
            acc[0] += w * bflo(v.x); acc[1] += w * bfhi(v.x);
            acc[2] += w * bflo(v.y); acc[3] += w * bfhi(v.y);
            acc[4] += w * bflo(v.z); acc[5] += w * bfhi(v.z);
            acc[6] += w * bflo(v.w); acc[7] += w * bfhi(v.w);
        }
        #pragma unroll
        for (int k = 0; k < 8; k++) s_red[g][k][c8] = acc[k];
        __syncthreads();

        if (t < 16) {
            float inv = 1.0f / s_den;
            float o[8];
            #pragma unroll
            for (int k = 0; k < 8; k++) {
                float ss = 0.0f;
                #pragma unroll
                for (int gg = 0; gg < 16; gg++) ss += s_red[gg][k][t];
                float v = ss * inv + b2[t * 8 + k];
                o[k] = v > 0.0f ? v : 0.01f * v;
            }
            float4* dst = (float4*)&out[(size_t)i * OUT2 + t * 8];
            dst[0] = make_float4(o[0], o[1], o[2], o[3]);
            dst[1] = make_float4(o[4], o[5], o[6], o[7]);
        }
    }
}

// ---------------- launch ----------------
extern "C" void kernel_launch(void* const* d_in, const int* in_sizes, int n_in,
                              void* d_out, int out_size) {
    const float* x   = (const float*)d_in[0];
    const float* adj = (const float*)d_in[1];
    const float* w1  = (const float*)d_in[2];
    const float* as1 = (const float*)d_in[3];
    const float* ad1 = (const float*)d_in[4];
    const float* b1  = (const float*)d_in[5];
    const float* w2  = (const float*)d_in[6];
    const float* as2 = (const float*)d_in[7];
    const float* ad2 = (const float*)d_in[8];
    const float* b2  = (const float*)d_in[9];
    float* out = (float*)d_out;

    float *h1p, *hmidp, *h2p, *asrc1p, *adst1p, *p2sp, *p2dp;
    __nv_bfloat162 *h1bp, *h2bp;
    cudaGetSymbolAddress((void**)&h1p,    g_h1);
    cudaGetSymbolAddress((void**)&hmidp,  g_hmid);
    cudaGetSymbolAddress((void**)&h2p,    g_h2);
    cudaGetSymbolAddress((void**)&h1bp,   g_h1b);
    cudaGetSymbolAddress((void**)&h2bp,   g_h2b);
    cudaGetSymbolAddress((void**)&asrc1p, g_asrc1);
    cudaGetSymbolAddress((void**)&adst1p, g_adst1);
    cudaGetSymbolAddress((void**)&p2sp,   g_p2s);
    cudaGetSymbolAddress((void**)&p2dp,   g_p2d);

    build_csr<<<NN, 256>>>(adj);

    // h1 = x @ w1 (tf32 MMA + bf16 copy + fused scores1), BK=32
    gemm_tf32<64, 128, 32, 32, 32, 2, 4, 2, true><<<dim3(C1 / 128, NN / 64), 256>>>(
        x, w1, h1p, h1bp, as1, ad1, asrc1p, adst1p, NN, C1, FIN);

    agg1<<<NN, C1>>>(b1);

    // h2 = hmid @ w2 (tf32 MMA + bf16 copy + fused score partials), BK=64
    gemm_tf32<32, 64, 64, 16, 16, 1, 2, 1, false><<<dim3(OUT2 / 64, NN / 32), 256>>>(
        hmidp, w2, h2p, h2bp, as2, ad2, p2sp, p2dp, NN, OUT2, C1);

    agg2<<<NN, 256>>>(b2, out);
}